// round 12
// baseline (speedup 1.0000x reference)
#include <cuda_runtime.h>

// Shapes (fixed):
//   state: [64, 128, 16]
//   block1: cols=16   -> x1 [64, 128ch, 124]   (kernel 1, materialized)
//   block2: cols=128  -> x2 [64, 1024ch, 120]  (fused)
//   block3: cols=1024 -> x3 [64, 8192ch, 116]  (fused with dense, never stored)
//   dense:  feat = t*8192 + ch3, W [950272,2], out = tanh(x@W + bd) -> [64, 2]

#define Bz   64
#define Lin  128
#define Cin  16
#define KW   5
#define NF   8
#define L1   124
#define CH1  128
#define L2   120
#define CH2  1024
#define L3   116
#define CH3  8192
#define TH   58            // t-half length (L3/2)
#define TH2  60            // padded to multiple of 5 for rotation unroll
#define XPP  65            // xp pitch in pairs (odd; reads reach index 64)
#define BH   32            // batches per CTA (batch-halved)

__device__ float g_x1[Bz * CH1 * L1];     // 4.06 MB
__device__ float g_partial[128 * 32];     // [b*2+a] stride 128B -> distinct L2 lines
__device__ unsigned int g_done;

// ---------------------------------------------------------------------------
typedef unsigned long long u64p;
union pk2 { u64p u; float2 f; uint2 h; int2 i; };

__device__ __forceinline__ u64p f2pk(float lo, float hi) {
    pk2 x; x.f.x = lo; x.f.y = hi; return x.u;
}
__device__ __forceinline__ u64p f2fma(u64p a, u64p b, u64p c) {
    u64p d; asm("fma.rn.f32x2 %0, %1, %2, %3;" : "=l"(d) : "l"(a), "l"(b), "l"(c)); return d;
}
// relu per fp32 half via signed-int max: max(x,0.f) == s32max(bits,0) for IEEE fp32.
__device__ __forceinline__ u64p i2relu(u64p v) {
    pk2 x; x.u = v;
    x.i.x = max(x.i.x, 0);
    x.i.y = max(x.i.y, 0);
    return x.u;
}

// ---------------------------------------------------------------------------
// Block 1: one CTA per (c, b). Also resets the reduction scratch.
// ---------------------------------------------------------------------------
__global__ void k_block1(const float* __restrict__ state,
                         const float* __restrict__ k1,
                         const float* __restrict__ b1) {
    const int c = blockIdx.x, b = blockIdx.y, tid = threadIdx.x;

    if (blockIdx.x == 0 && blockIdx.y == 0) {
        for (int j = tid; j < 128 * 32; j += 128) g_partial[j] = 0.f;
        if (tid == 0) g_done = 0u;
    }

    __shared__ float ssh[Lin];
    __shared__ float wsh[KW * NF];
    __shared__ float bsh[NF];

    ssh[tid] = state[(b * Lin + tid) * Cin + c];
    if (tid < KW * NF) wsh[tid] = k1[(tid >> 3) * CH1 + c * NF + (tid & 7)];
    if (tid < NF)      bsh[tid] = b1[c * NF + tid];
    __syncthreads();

    for (int i = tid; i < NF * L1; i += 128) {
        int f = i / L1, t = i - f * L1;
        float y = bsh[f];
        #pragma unroll
        for (int k = 0; k < KW; k++) y = fmaf(ssh[t + k], wsh[k * NF + f], y);
        g_x1[(b * CH1 + c * NF + f) * L1 + t] = fmaxf(y, 0.f);
    }
}

// ---------------------------------------------------------------------------
// Fused block2+block3+dense+epilogue.
// Grid (1024 groups, 2 batch-halves); 128 threads = (b:32) x (fp:4).
// t-half packing: packed reg = (val@t, val@t+58). Unroll-5 register rotation.
// ---------------------------------------------------------------------------
__global__ void __launch_bounds__(128, 8) k_fused(
        const float* __restrict__ k2, const float* __restrict__ b2,
        const float* __restrict__ k3, const float* __restrict__ b3,
        const float* __restrict__ W,
        const float* __restrict__ bd, float* __restrict__ out) {
    const int g = blockIdx.x, bh = blockIdx.y, tid = threadIdx.x;
    const int c = g >> 3;

    __shared__ u64p       xp[BH * XPP];        // 16640 B
    __shared__ ulonglong2 Wp[TH2 * 4 * 2];     // 7680 B: [(s*4+fp)*2 + {0,1}]
    __shared__ float      x1ch[8 * L1];        // 3968 B staging
    __shared__ unsigned   lastf;

    // ---- zero xp (pad slots must be finite-zero) ----
    for (int i = tid; i < BH * XPP; i += 128) xp[i] = 0ull;

    // ---- W -> t-half-packed smem; rows s>=58 zeroed (pad iterations) ----
    const float4* __restrict__ W4 = (const float4*)W;
    for (int i = tid; i < TH2 * 4; i += 128) {
        int s = i >> 2, fp = i & 3;
        if (s < TH) {
            float4 va = W4[s * 4096 + g * 4 + fp];          // t = s
            float4 vb = W4[(s + TH) * 4096 + g * 4 + fp];   // t = s + 58
            Wp[2 * i]     = make_ulonglong2(f2pk(va.x, vb.x), f2pk(va.y, vb.y)); // f0
            Wp[2 * i + 1] = make_ulonglong2(f2pk(va.z, vb.z), f2pk(va.w, vb.w)); // f1
        } else {
            Wp[2 * i]     = make_ulonglong2(0ull, 0ull);
            Wp[2 * i + 1] = make_ulonglong2(0ull, 0ull);
        }
    }

    // ---- block2 weights (broadcast) ----
    float w2r[KW];
    #pragma unroll
    for (int k = 0; k < KW; k++) w2r[k] = k2[k * CH2 + g];
    const float b2g = b2[g];

    // ---- Phase A: x2 for this CTA's 32 batches, 4 chunks of 8 ----
    for (int cc = 0; cc < 4; cc++) {
        for (int i = tid; i < 8 * L1; i += 128) {
            int bl = i / L1, t = i - bl * L1;
            x1ch[i] = g_x1[((bh * BH + cc * 8 + bl) * CH1 + c) * L1 + t];
        }
        __syncthreads();
        for (int i = tid; i < 8 * L2; i += 128) {
            int bl = i / L2, t = i - bl * L2;
            float y = b2g;
            #pragma unroll
            for (int k = 0; k < KW; k++) y = fmaf(x1ch[bl * L1 + t + k], w2r[k], y);
            y = fmaxf(y, 0.f);
            float* row = (float*)&xp[(cc * 8 + bl) * XPP];
            if (t < TH + 4) row[t * 2] = y;              // lo half: p = t   (t < 62)
            if (t >= TH)    row[(t - TH) * 2 + 1] = y;   // hi half: p = t - 58
        }
        __syncthreads();
    }

    // ---- hoisted block3 weights/bias, broadcast-packed per filter ----
    const int b  = tid >> 2;          // 0..31 (CTA-local batch)
    const int fp = tid & 3;
    const int f0 = g * NF + 2 * fp;

    const u64p wA0 = f2pk(k3[0 * CH3 + f0], k3[0 * CH3 + f0]);
    const u64p wA1 = f2pk(k3[1 * CH3 + f0], k3[1 * CH3 + f0]);
    const u64p wA2 = f2pk(k3[2 * CH3 + f0], k3[2 * CH3 + f0]);
    const u64p wA3 = f2pk(k3[3 * CH3 + f0], k3[3 * CH3 + f0]);
    const u64p wA4 = f2pk(k3[4 * CH3 + f0], k3[4 * CH3 + f0]);
    const u64p wB0 = f2pk(k3[0 * CH3 + f0 + 1], k3[0 * CH3 + f0 + 1]);
    const u64p wB1 = f2pk(k3[1 * CH3 + f0 + 1], k3[1 * CH3 + f0 + 1]);
    const u64p wB2 = f2pk(k3[2 * CH3 + f0 + 1], k3[2 * CH3 + f0 + 1]);
    const u64p wB3 = f2pk(k3[3 * CH3 + f0 + 1], k3[3 * CH3 + f0 + 1]);
    const u64p wB4 = f2pk(k3[4 * CH3 + f0 + 1], k3[4 * CH3 + f0 + 1]);
    const u64p bA  = f2pk(b3[f0], b3[f0]);
    const u64p bB  = f2pk(b3[f0 + 1], b3[f0 + 1]);

    // ---- Phase B: 60 iterations, unroll-5 register rotation (no window MOVs) ----
    const u64p*       xc = &xp[b * XPP];
    const ulonglong2* wc = &Wp[fp * 2];

    u64p x0 = xc[0], x1 = xc[1], x2 = xc[2], x3 = xc[3], x4 = xc[4];
    u64p acc0 = 0ull, acc1 = 0ull;

#define STEP(J, XA, XB, XC, XD, XE) do {                                  \
        u64p ya = bA, yb = bB;                                            \
        ya = f2fma(XA, wA0, ya);  yb = f2fma(XA, wB0, yb);                \
        ya = f2fma(XB, wA1, ya);  yb = f2fma(XB, wB1, yb);                \
        ya = f2fma(XC, wA2, ya);  yb = f2fma(XC, wB2, yb);                \
        ya = f2fma(XD, wA3, ya);  yb = f2fma(XD, wB3, yb);                \
        ya = f2fma(XE, wA4, ya);  yb = f2fma(XE, wB4, yb);                \
        ya = i2relu(ya);          yb = i2relu(yb);                        \
        ulonglong2 w0 = wc[(J) * 8];                                      \
        ulonglong2 w1 = wc[(J) * 8 + 1];                                  \
        acc0 = f2fma(ya, w0.x, acc0);  acc1 = f2fma(ya, w0.y, acc1);      \
        acc0 = f2fma(yb, w1.x, acc0);  acc1 = f2fma(yb, w1.y, acc1);      \
        XA = xc[(J) + 5];                                                 \
    } while (0)

    for (int it = 0; it < TH2 / 5; it++) {
        STEP(0, x0, x1, x2, x3, x4);
        STEP(1, x1, x2, x3, x4, x0);
        STEP(2, x2, x3, x4, x0, x1);
        STEP(3, x3, x4, x0, x1, x2);
        STEP(4, x4, x0, x1, x2, x3);
        xc += 5;
        wc += 40;
    }
#undef STEP

    pk2 r0, r1; r0.u = acc0; r1.u = acc1;
    float s0 = r0.f.x + r0.f.y;          // halves = disjoint t ranges
    float s1 = r1.f.x + r1.f.y;

    // sum the 4 fp lanes sharing a batch
    s0 += __shfl_down_sync(0xffffffffu, s0, 2);
    s0 += __shfl_down_sync(0xffffffffu, s0, 1);
    s1 += __shfl_down_sync(0xffffffffu, s1, 2);
    s1 += __shfl_down_sync(0xffffffffu, s1, 1);
    if (fp == 0) {
        const int gb = bh * BH + b;
        atomicAdd(&g_partial[(gb * 2 + 0) * 32], s0);
        atomicAdd(&g_partial[(gb * 2 + 1) * 32], s1);
    }

    // ---- last-CTA epilogue ----
    __syncthreads();
    if (tid == 0) {
        __threadfence();
        lastf = (atomicAdd(&g_done, 1u) == (unsigned)(gridDim.x * gridDim.y - 1));
    }
    __syncthreads();
    if (lastf) {
        __threadfence();
        float v = *((volatile float*)&g_partial[tid * 32]);
        out[tid] = tanhf(v + bd[tid & 1]);
    }
}

// ---------------------------------------------------------------------------
extern "C" void kernel_launch(void* const* d_in, const int* in_sizes, int n_in,
                              void* d_out, int out_size) {
    const float* state = (const float*)d_in[0];
    const float* k1    = (const float*)d_in[1];
    const float* b1    = (const float*)d_in[2];
    const float* k2    = (const float*)d_in[3];
    const float* b2    = (const float*)d_in[4];
    const float* k3    = (const float*)d_in[5];
    const float* b3    = (const float*)d_in[6];
    const float* W     = (const float*)d_in[7];
    const float* bd    = (const float*)d_in[8];
    float* out = (float*)d_out;

    k_block1<<<dim3(16, 64), 128>>>(state, k1, b1);
    k_fused<<<dim3(1024, 2), 128>>>(k2, b2, k3, b3, W, bd, out);
}

// round 16
// speedup vs baseline: 1.0375x; 1.0375x over previous
#include <cuda_runtime.h>

// Shapes (fixed):
//   state: [64, 128, 16]
//   block1: cols=16   -> x1 [64, 128ch, 124]   (kernel 1, materialized)
//   block2: cols=128  -> x2 [64, 1024ch, 120]  (fused)
//   block3: cols=1024 -> x3 [64, 8192ch, 116]  (fused with dense, never stored)
//   dense:  feat = t*8192 + ch3, W [950272,2], out = tanh(x@W + bd) -> [64, 2]

#define Bz   64
#define Lin  128
#define Cin  16
#define KW   5
#define NF   8
#define L1   124
#define CH1  128
#define L2   120
#define CH2  1024
#define L3   116
#define CH3  8192
#define TH   58            // t-half length (L3/2)
#define TH2  60            // iteration count (padded, multiple of 10 for pipeline unroll)
#define TH3  61            // Wp rows incl. prefetch-overrun pad
#define XPP  65            // xp pitch in pairs (odd; window reads reach index 64)

__device__ float g_x1[Bz * CH1 * L1];     // 4.06 MB
__device__ float g_partial[128 * 32];     // [b*2+a] stride 128B -> distinct L2 lines
__device__ unsigned int g_done;

// ---------------------------------------------------------------------------
typedef unsigned long long u64p;
union pk2 { u64p u; float2 f; uint2 h; int2 i; };

__device__ __forceinline__ u64p f2pk(float lo, float hi) {
    pk2 x; x.f.x = lo; x.f.y = hi; return x.u;
}
__device__ __forceinline__ u64p f2fma(u64p a, u64p b, u64p c) {
    u64p d; asm("fma.rn.f32x2 %0, %1, %2, %3;" : "=l"(d) : "l"(a), "l"(b), "l"(c)); return d;
}
// relu per fp32 half via signed-int max: max(x,0.f) == s32max(bits,0) for IEEE fp32.
__device__ __forceinline__ u64p i2relu(u64p v) {
    pk2 x; x.u = v;
    x.i.x = max(x.i.x, 0);
    x.i.y = max(x.i.y, 0);
    return x.u;
}

// ---------------------------------------------------------------------------
// Block 1: one CTA per (c, b). Also resets the reduction scratch.
// ---------------------------------------------------------------------------
__global__ void k_block1(const float* __restrict__ state,
                         const float* __restrict__ k1,
                         const float* __restrict__ b1) {
    const int c = blockIdx.x, b = blockIdx.y, tid = threadIdx.x;

    if (blockIdx.x == 0 && blockIdx.y == 0) {
        for (int j = tid; j < 128 * 32; j += 128) g_partial[j] = 0.f;
        if (tid == 0) g_done = 0u;
    }

    __shared__ float ssh[Lin];
    __shared__ float wsh[KW * NF];
    __shared__ float bsh[NF];

    ssh[tid] = state[(b * Lin + tid) * Cin + c];
    if (tid < KW * NF) wsh[tid] = k1[(tid >> 3) * CH1 + c * NF + (tid & 7)];
    if (tid < NF)      bsh[tid] = b1[c * NF + tid];
    __syncthreads();

    for (int i = tid; i < NF * L1; i += 128) {
        int f = i / L1, t = i - f * L1;
        float y = bsh[f];
        #pragma unroll
        for (int k = 0; k < KW; k++) y = fmaf(ssh[t + k], wsh[k * NF + f], y);
        g_x1[(b * CH1 + c * NF + f) * L1 + t] = fmaxf(y, 0.f);
    }
}

// ---------------------------------------------------------------------------
// Fused block2+block3+dense+epilogue. Grid 1024; 256 threads = (b:64) x (fp:4).
// t-half packing (reg = val@(t, t+58)); unroll-10 blocks with register-rotated
// sliding window (period 5) AND double-buffered W prefetch (period 2).
// ---------------------------------------------------------------------------
__global__ void __launch_bounds__(256, 4) k_fused(
        const float* __restrict__ k2, const float* __restrict__ b2,
        const float* __restrict__ k3, const float* __restrict__ b3,
        const float* __restrict__ W,
        const float* __restrict__ bd, float* __restrict__ out) {
    const int g = blockIdx.x, tid = threadIdx.x;
    const int c = g >> 3;

    __shared__ u64p       xp[Bz * XPP];        // 33280 B
    __shared__ ulonglong2 Wp[TH3 * 4 * 2];     // 7808 B: [(s*4+fp)*2 + {0,1}]
    __shared__ float      x1ch[16 * L1];       // 7936 B staging
    __shared__ unsigned   lastf;

    // ---- zero xp (pad slots must be finite-zero) ----
    for (int i = tid; i < Bz * XPP; i += 256) xp[i] = 0ull;

    // ---- W -> t-half-packed smem; rows s>=58 zeroed (pad / prefetch overrun) ----
    const float4* __restrict__ W4 = (const float4*)W;
    for (int i = tid; i < TH3 * 4; i += 256) {
        int s = i >> 2, fp = i & 3;
        if (s < TH) {
            float4 va = W4[s * 4096 + g * 4 + fp];          // t = s
            float4 vb = W4[(s + TH) * 4096 + g * 4 + fp];   // t = s + 58
            Wp[2 * i]     = make_ulonglong2(f2pk(va.x, vb.x), f2pk(va.y, vb.y)); // f0
            Wp[2 * i + 1] = make_ulonglong2(f2pk(va.z, vb.z), f2pk(va.w, vb.w)); // f1
        } else {
            Wp[2 * i]     = make_ulonglong2(0ull, 0ull);
            Wp[2 * i + 1] = make_ulonglong2(0ull, 0ull);
        }
    }

    // ---- block2 weights (broadcast) ----
    float w2r[KW];
    #pragma unroll
    for (int k = 0; k < KW; k++) w2r[k] = k2[k * CH2 + g];
    const float b2g = b2[g];

    // ---- Phase A: x2[b,g,:] packed into xp, 4 chunks of 16 batches ----
    for (int cc = 0; cc < 4; cc++) {
        for (int i = tid; i < 16 * L1; i += 256) {
            int bl = i / L1, t = i - bl * L1;
            x1ch[i] = g_x1[((cc * 16 + bl) * CH1 + c) * L1 + t];
        }
        __syncthreads();
        for (int i = tid; i < 16 * L2; i += 256) {
            int bl = i / L2, t = i - bl * L2;
            float y = b2g;
            #pragma unroll
            for (int k = 0; k < KW; k++) y = fmaf(x1ch[bl * L1 + t + k], w2r[k], y);
            y = fmaxf(y, 0.f);
            float* row = (float*)&xp[(cc * 16 + bl) * XPP];
            if (t < TH + 4) row[t * 2] = y;              // lo half: p = t   (t < 62)
            if (t >= TH)    row[(t - TH) * 2 + 1] = y;   // hi half: p = t - 58
        }
        __syncthreads();
    }

    // ---- hoisted block3 weights/bias, broadcast-packed per filter ----
    const int b  = tid >> 2;          // 0..63
    const int fp = tid & 3;
    const int f0 = g * NF + 2 * fp;

    const u64p wA0 = f2pk(k3[0 * CH3 + f0], k3[0 * CH3 + f0]);
    const u64p wA1 = f2pk(k3[1 * CH3 + f0], k3[1 * CH3 + f0]);
    const u64p wA2 = f2pk(k3[2 * CH3 + f0], k3[2 * CH3 + f0]);
    const u64p wA3 = f2pk(k3[3 * CH3 + f0], k3[3 * CH3 + f0]);
    const u64p wA4 = f2pk(k3[4 * CH3 + f0], k3[4 * CH3 + f0]);
    const u64p wB0 = f2pk(k3[0 * CH3 + f0 + 1], k3[0 * CH3 + f0 + 1]);
    const u64p wB1 = f2pk(k3[1 * CH3 + f0 + 1], k3[1 * CH3 + f0 + 1]);
    const u64p wB2 = f2pk(k3[2 * CH3 + f0 + 1], k3[2 * CH3 + f0 + 1]);
    const u64p wB3 = f2pk(k3[3 * CH3 + f0 + 1], k3[3 * CH3 + f0 + 1]);
    const u64p wB4 = f2pk(k3[4 * CH3 + f0 + 1], k3[4 * CH3 + f0 + 1]);
    const u64p bA  = f2pk(b3[f0], b3[f0]);
    const u64p bB  = f2pk(b3[f0 + 1], b3[f0 + 1]);

    // ---- Phase B: 60 steps = 6 unrolled blocks of 10.
    //      Window regs rotate period-5; W double-buffers rotate period-2. ----
    const u64p*       xc = &xp[b * XPP];
    const ulonglong2* wc = &Wp[fp * 2];

    u64p x0 = xc[0], x1 = xc[1], x2 = xc[2], x3 = xc[3], x4 = xc[4];
    u64p acc0 = 0ull, acc1 = 0ull, acc2 = 0ull, acc3 = 0ull;

    ulonglong2 wpa = wc[0], wqa = wc[1];   // buffer set A holds step-0 weights
    ulonglong2 wpb, wqb;                   // buffer set B

    // STEP J: prefetch step J+1 weights into WN*, compute with WC*.
#define STEP(J, XA, XB, XC, XD, XE, WCP, WCQ, WNP, WNQ) do {              \
        WNP = wc[((J) + 1) * 8];                                          \
        WNQ = wc[((J) + 1) * 8 + 1];                                      \
        u64p ya = f2fma(XA, wA0, bA);                                     \
        u64p yb = f2fma(XA, wB0, bB);                                     \
        ya = f2fma(XB, wA1, ya);  yb = f2fma(XB, wB1, yb);                \
        ya = f2fma(XC, wA2, ya);  yb = f2fma(XC, wB2, yb);                \
        ya = f2fma(XD, wA3, ya);  yb = f2fma(XD, wB3, yb);                \
        ya = f2fma(XE, wA4, ya);  yb = f2fma(XE, wB4, yb);                \
        ya = i2relu(ya);          yb = i2relu(yb);                        \
        acc0 = f2fma(ya, WCP.x, acc0);  acc1 = f2fma(ya, WCP.y, acc1);    \
        acc2 = f2fma(yb, WCQ.x, acc2);  acc3 = f2fma(yb, WCQ.y, acc3);    \
        XA = xc[(J) + 5];                                                 \
    } while (0)

    #pragma unroll 1
    for (int blk = 0; blk < TH2 / 10; blk++) {
        STEP(0, x0, x1, x2, x3, x4, wpa, wqa, wpb, wqb);
        STEP(1, x1, x2, x3, x4, x0, wpb, wqb, wpa, wqa);
        STEP(2, x2, x3, x4, x0, x1, wpa, wqa, wpb, wqb);
        STEP(3, x3, x4, x0, x1, x2, wpb, wqb, wpa, wqa);
        STEP(4, x4, x0, x1, x2, x3, wpa, wqa, wpb, wqb);
        STEP(5, x0, x1, x2, x3, x4, wpb, wqb, wpa, wqa);
        STEP(6, x1, x2, x3, x4, x0, wpa, wqa, wpb, wqb);
        STEP(7, x2, x3, x4, x0, x1, wpb, wqb, wpa, wqa);
        STEP(8, x3, x4, x0, x1, x2, wpa, wqa, wpb, wqb);
        STEP(9, x4, x0, x1, x2, x3, wpb, wqb, wpa, wqa);
        xc += 10;
        wc += 80;
    }
#undef STEP

    pk2 r0, r1, r2, r3;
    r0.u = acc0; r1.u = acc1; r2.u = acc2; r3.u = acc3;
    float s0 = (r0.f.x + r0.f.y) + (r2.f.x + r2.f.y);   // action 0
    float s1 = (r1.f.x + r1.f.y) + (r3.f.x + r3.f.y);   // action 1

    // sum the 4 fp lanes sharing a batch
    s0 += __shfl_down_sync(0xffffffffu, s0, 2);
    s0 += __shfl_down_sync(0xffffffffu, s0, 1);
    s1 += __shfl_down_sync(0xffffffffu, s1, 2);
    s1 += __shfl_down_sync(0xffffffffu, s1, 1);
    if (fp == 0) {
        atomicAdd(&g_partial[(b * 2 + 0) * 32], s0);
        atomicAdd(&g_partial[(b * 2 + 1) * 32], s1);
    }

    // ---- last-CTA epilogue ----
    __syncthreads();
    if (tid == 0) {
        __threadfence();
        lastf = (atomicAdd(&g_done, 1u) == (unsigned)(gridDim.x - 1));
    }
    __syncthreads();
    if (lastf && tid < 128) {
        __threadfence();
        float v = *((volatile float*)&g_partial[tid * 32]);
        out[tid] = tanhf(v + bd[tid & 1]);
    }
}

// ---------------------------------------------------------------------------
extern "C" void kernel_launch(void* const* d_in, const int* in_sizes, int n_in,
                              void* d_out, int out_size) {
    const float* state = (const float*)d_in[0];
    const float* k1    = (const float*)d_in[1];
    const float* b1    = (const float*)d_in[2];
    const float* k2    = (const float*)d_in[3];
    const float* b2    = (const float*)d_in[4];
    const float* k3    = (const float*)d_in[5];
    const float* b3    = (const float*)d_in[6];
    const float* W     = (const float*)d_in[7];
    const float* bd    = (const float*)d_in[8];
    float* out = (float*)d_out;

    k_block1<<<dim3(16, 64), 128>>>(state, k1, b1);
    k_fused<<<1024, 256>>>(k2, b2, k3, b3, W, bd, out);
}